// round 16
// baseline (speedup 1.0000x reference)
#include <cuda_runtime.h>

#define F_DIM 128
#define NPG   100
#define KNUM  80
#define EPG   1600
#define EPG4  (EPG / 4)   // 400 int4 groups
#define TPB   256

__device__ __forceinline__ void stcs4(float* p, float4 v) {
    asm volatile("st.global.cs.v4.f32 [%0], {%1,%2,%3,%4};"
                 :: "l"(p), "f"(v.x), "f"(v.y), "f"(v.z), "f"(v.w) : "memory");
}
__device__ __forceinline__ void stcs1(float* p, float v) {
    asm volatile("st.global.cs.f32 [%0], %1;" :: "l"(p), "f"(v) : "memory");
}

__global__ __launch_bounds__(TPB, 8) void sagpool_fused_kernel(
    const float* __restrict__ x,
    const int*   __restrict__ ei,      // [2, E]: [0..E) = src, [E..2E) = dst
    const float* __restrict__ theta,   // [F]
    float* __restrict__ out,
    int E, int B)
{
    __shared__ float s[NPG];           // dot(x_i, theta); later self-loop term
    __shared__ float us[NPG];          // dis_i * s_i
    __shared__ float z[NPG];           // scatter accumulator -> final score
    __shared__ float dis[NPG];
    __shared__ int   degp[2][NPG];     // per-warp (warps 6,7) degree hists
    __shared__ __align__(16) int packed[EPG];   // (src-base) | (dst-base)<<7
    __shared__ float codef[NPG];       // kept ? (float)(bK+newid) : -1
    __shared__ int   inv[KNUM];
    __shared__ float scl[KNUM];
    __shared__ int   rpA[NPG];
    __shared__ int   rpB[NPG];
    __shared__ unsigned wbal[4];

    const unsigned FULL = 0xffffffffu;
    const int b     = blockIdx.x;
    const int t     = threadIdx.x;
    const int warp  = t >> 5, lane = t & 31;
    const int base  = b * NPG;
    const int ebase = b * EPG;
    const int bK    = b * KNUM;

    const size_t EOUT0 = (size_t)B * KNUM * F_DIM;
    const size_t EOUT1 = EOUT0 + (size_t)E;
    const size_t BOUT  = EOUT0 + 2 * (size_t)E;

    // independent output: batch ids
    if (t < KNUM) stcs1(out + BOUT + (size_t)bK + t, (float)b);

    // ================= Phase A: warp-specialized 6 dots / 2 edges =================
    if (warp < 6) {
        // 8 lanes per row, 4 rows (chunks) per warp-iter, butterfly reduce
        const int sub = lane & 7;         // lane within 8-group
        const int rg  = lane >> 3;        // row within chunk
        const float4* th4 = reinterpret_cast<const float4*>(theta);
        float4 t0 = th4[sub];
        float4 t1 = th4[sub + 8];
        float4 t2 = th4[sub + 16];
        float4 t3 = th4[sub + 24];

        // chunks c = warp, warp+6, ... (25 chunks of 4 rows); warp 0 gets chunk 24 too
        #pragma unroll 5
        for (int c = warp; c < 25; c += 6) {
            int row = c * 4 + rg;
            const float4* xr = reinterpret_cast<const float4*>(x + (size_t)(base + row) * F_DIM);
            float4 v0 = xr[sub];
            float4 v1 = xr[sub + 8];
            float4 v2 = xr[sub + 16];
            float4 v3 = xr[sub + 24];
            float dA = v0.x * t0.x + v0.y * t0.y + v0.z * t0.z + v0.w * t0.w;
            float dB = v1.x * t1.x + v1.y * t1.y + v1.z * t1.z + v1.w * t1.w;
            dA += v2.x * t2.x + v2.y * t2.y + v2.z * t2.z + v2.w * t2.w;
            dB += v3.x * t3.x + v3.y * t3.y + v3.z * t3.z + v3.w * t3.w;
            float d = dA + dB;
            d += __shfl_xor_sync(FULL, d, 4);
            d += __shfl_xor_sync(FULL, d, 2);
            d += __shfl_xor_sync(FULL, d, 1);
            if (sub == 0) s[row] = d;
        }
    } else {
        // warps 6,7: init z + hist, load+pack 200 int4-groups each, degree histogram
        const int w = warp - 6;            // 0..1
        for (int i = lane; i < NPG; i += 32) {
            degp[w][i] = 0;
            if (w == 0) z[i] = 0.0f;
        }
        __syncwarp();

        const int4* src4 = reinterpret_cast<const int4*>(ei + ebase);
        const int4* dst4 = reinterpret_cast<const int4*>(ei + (size_t)E + ebase);
        const int gbase = w * 200;         // groups [gbase, gbase+200)
        #pragma unroll
        for (int q0 = 0; q0 < 200; q0 += 32) {
            int qi = q0 + lane;            // 0..199 (+ partial tail 192..199)
            unsigned act = __ballot_sync(FULL, qi < 200);
            if (qi < 200) {
                int q = gbase + qi;
                int4 sv = src4[q]; int4 dv = dst4[q];
                int4 pk;
                pk.x = (sv.x - base) | ((dv.x - base) << 7);
                pk.y = (sv.y - base) | ((dv.y - base) << 7);
                pk.z = (sv.z - base) | ((dv.z - base) << 7);
                pk.w = (sv.w - base) | ((dv.w - base) << 7);
                reinterpret_cast<int4*>(packed)[q] = pk;
                int vals[4] = { pk.x & 127, pk.y & 127, pk.z & 127, pk.w & 127 };
                #pragma unroll
                for (int c = 0; c < 4; c++) {
                    unsigned grp = __match_any_sync(act, vals[c]);
                    if ((grp & ((1u << lane) - 1u)) == 0)
                        degp[w][vals[c]] += __popc(grp);
                }
            }
        }
    }
    __syncthreads();

    // ================= per-node: deg, dis, us, self term =================
    if (t < NPG) {
        int d = 1 + degp[0][t] + degp[1][t];
        float fd = (float)d;
        float r  = rsqrtf(fd);
        float sv = s[t];
        dis[t] = r;
        us[t]  = r * sv;
        s[t]   = sv / fd;
    }
    __syncthreads();

    // ================= z[dst] += dis[src]*s[src] : two static blocks =================
    {
        int4 pkA = reinterpret_cast<const int4*>(packed)[t];
        bool hasB = (t + 256) < EPG4;
        int4 pkB = hasB ? reinterpret_cast<const int4*>(packed)[t + 256] : make_int4(0,0,0,0);

        atomicAdd(&z[(pkA.x >> 7) & 127], us[pkA.x & 127]);
        atomicAdd(&z[(pkA.y >> 7) & 127], us[pkA.y & 127]);
        atomicAdd(&z[(pkA.z >> 7) & 127], us[pkA.z & 127]);
        atomicAdd(&z[(pkA.w >> 7) & 127], us[pkA.w & 127]);
        if (hasB) {
            atomicAdd(&z[(pkB.x >> 7) & 127], us[pkB.x & 127]);
            atomicAdd(&z[(pkB.y >> 7) & 127], us[pkB.y & 127]);
            atomicAdd(&z[(pkB.z >> 7) & 127], us[pkB.z & 127]);
            atomicAdd(&z[(pkB.w >> 7) & 127], us[pkB.w & 127]);
        }
    }
    __syncthreads();

    if (t < NPG) z[t] = s[t] + dis[t] * z[t];
    __syncthreads();

    // ================= rank counting, split j-halves =================
    if (t < NPG) {
        float zi = z[t]; int r = 0;
        #pragma unroll 5
        for (int j = 0; j < NPG / 2; j++) {
            float zj = z[j];
            r += (zj > zi) || (zj == zi && j < t);
        }
        rpA[t] = r;
    } else if (t >= 128 && t < 128 + NPG) {
        int i = t - 128;
        float zi = z[i]; int r = 0;
        #pragma unroll 5
        for (int j = NPG / 2; j < NPG; j++) {
            float zj = z[j];
            r += (zj > zi) || (zj == zi && j < i);
        }
        rpB[i] = r;
    }
    __syncthreads();

    // ================= kept flags (registers) + ballots =================
    int k = 0;
    if (t < 128) {
        k = (t < NPG) ? ((rpA[t] + rpB[t]) < KNUM) : 0;
        unsigned bal = __ballot_sync(FULL, k);
        if (lane == 0) wbal[warp] = bal;
    }
    __syncthreads();

    // ================= scan -> codef, inv, scl =================
    if (t < NPG) {
        int off = __popc(wbal[warp] & ((1u << lane) - 1u));
        #pragma unroll
        for (int w = 0; w < 4; w++) if (w < warp) off += __popc(wbal[w]);
        codef[t] = k ? (float)(bK + off) : -1.0f;
        if (k) {
            inv[off] = t;
            scl[off] = 1.0f / (1.0f + __expf(-z[t]));
        }
    }
    __syncthreads();

    // ================= outputs: [x_new | edge0 | edge1] =================
    // x_new: 10 rows per warp, unrolled x2 (two LDG.128 in flight)
    #pragma unroll
    for (int rr = 0; rr < 10; rr += 2) {
        int r0 = warp + 8 * rr, r1 = warp + 8 * (rr + 1);
        int i0 = inv[r0],       i1 = inv[r1];
        float sc0 = scl[r0],    sc1 = scl[r1];
        float4 v0 = reinterpret_cast<const float4*>(x + (size_t)(base + i0) * F_DIM)[lane];
        float4 v1 = reinterpret_cast<const float4*>(x + (size_t)(base + i1) * F_DIM)[lane];
        v0.x *= sc0; v0.y *= sc0; v0.z *= sc0; v0.w *= sc0;
        v1.x *= sc1; v1.y *= sc1; v1.z *= sc1; v1.w *= sc1;
        stcs4(out + (size_t)(bK + r0) * F_DIM + lane * 4, v0);
        stcs4(out + (size_t)(bK + r1) * F_DIM + lane * 4, v1);
    }

    // relabeled edges via codef: two static blocks
    float* e0out = out + EOUT0 + ebase;
    float* e1out = out + EOUT1 + ebase;
    {
        int4 pk = reinterpret_cast<const int4*>(packed)[t];
        float4 o0, o1; float cs, cd;
        cs = codef[pk.x & 127]; cd = codef[(pk.x >> 7) & 127];
        o0.x = (cd < 0.0f) ? -1.0f : cs;  o1.x = (cs < 0.0f) ? -1.0f : cd;
        cs = codef[pk.y & 127]; cd = codef[(pk.y >> 7) & 127];
        o0.y = (cd < 0.0f) ? -1.0f : cs;  o1.y = (cs < 0.0f) ? -1.0f : cd;
        cs = codef[pk.z & 127]; cd = codef[(pk.z >> 7) & 127];
        o0.z = (cd < 0.0f) ? -1.0f : cs;  o1.z = (cs < 0.0f) ? -1.0f : cd;
        cs = codef[pk.w & 127]; cd = codef[(pk.w >> 7) & 127];
        o0.w = (cd < 0.0f) ? -1.0f : cs;  o1.w = (cs < 0.0f) ? -1.0f : cd;
        stcs4(e0out + t * 4, o0);
        stcs4(e1out + t * 4, o1);
    }
    if (t + 256 < EPG4) {
        int q = t + 256;
        int4 pk = reinterpret_cast<const int4*>(packed)[q];
        float4 o0, o1; float cs, cd;
        cs = codef[pk.x & 127]; cd = codef[(pk.x >> 7) & 127];
        o0.x = (cd < 0.0f) ? -1.0f : cs;  o1.x = (cs < 0.0f) ? -1.0f : cd;
        cs = codef[pk.y & 127]; cd = codef[(pk.y >> 7) & 127];
        o0.y = (cd < 0.0f) ? -1.0f : cs;  o1.y = (cs < 0.0f) ? -1.0f : cd;
        cs = codef[pk.z & 127]; cd = codef[(pk.z >> 7) & 127];
        o0.z = (cd < 0.0f) ? -1.0f : cs;  o1.z = (cs < 0.0f) ? -1.0f : cd;
        cs = codef[pk.w & 127]; cd = codef[(pk.w >> 7) & 127];
        o0.w = (cd < 0.0f) ? -1.0f : cs;  o1.w = (cs < 0.0f) ? -1.0f : cd;
        stcs4(e0out + q * 4, o0);
        stcs4(e1out + q * 4, o1);
    }
}

extern "C" void kernel_launch(void* const* d_in, const int* in_sizes, int n_in,
                              void* d_out, int out_size)
{
    const float* x     = (const float*)d_in[0];
    const int*   ei    = (const int*)d_in[1];
    const float* theta = (const float*)d_in[3];
    float* out = (float*)d_out;

    int N = in_sizes[0] / F_DIM;   // 100000
    int E = in_sizes[1] / 2;       // 1600000
    int B = N / NPG;               // 1000

    sagpool_fused_kernel<<<B, TPB>>>(x, ei, theta, out, E, B);
}

// round 17
// speedup vs baseline: 1.0749x; 1.0749x over previous
#include <cuda_runtime.h>

#define F_DIM 128
#define NPG   100
#define KNUM  80
#define EPG   1600
#define EPG4  (EPG / 4)   // 400 int4 groups
#define TPB   256

__device__ __forceinline__ void stcs4(float* p, float4 v) {
    asm volatile("st.global.cs.v4.f32 [%0], {%1,%2,%3,%4};"
                 :: "l"(p), "f"(v.x), "f"(v.y), "f"(v.z), "f"(v.w) : "memory");
}
__device__ __forceinline__ void stcs1(float* p, float v) {
    asm volatile("st.global.cs.f32 [%0], %1;" :: "l"(p), "f"(v) : "memory");
}

__global__ __launch_bounds__(TPB, 8) void sagpool_fused_kernel(
    const float* __restrict__ x,
    const int*   __restrict__ ei,      // [2, E]: [0..E) = src, [E..2E) = dst
    const float* __restrict__ theta,   // [F]
    float* __restrict__ out,
    int E, int B)
{
    __shared__ float s[NPG];           // dot(x_i, theta); later self-loop term
    __shared__ float us[NPG];          // dis_i * s_i
    __shared__ float z[NPG];           // scatter accumulator -> final score
    __shared__ float dis[NPG];
    __shared__ int   degp[2][NPG];     // per-warp (warps 6,7) degree hists
    __shared__ __align__(16) int packed[EPG];   // (src-base) | (dst-base)<<7
    __shared__ float codef[NPG];       // kept ? (float)(bK+newid) : -1
    __shared__ int   inv[KNUM];
    __shared__ float scl[KNUM];
    __shared__ int   rpA[NPG];
    __shared__ int   rpB[NPG];
    __shared__ unsigned wbal[4];

    const unsigned FULL = 0xffffffffu;
    const int b     = blockIdx.x;
    const int t     = threadIdx.x;
    const int warp  = t >> 5, lane = t & 31;
    const int base  = b * NPG;
    const int ebase = b * EPG;
    const int bK    = b * KNUM;

    const size_t EOUT0 = (size_t)B * KNUM * F_DIM;
    const size_t EOUT1 = EOUT0 + (size_t)E;
    const size_t BOUT  = EOUT0 + 2 * (size_t)E;

    // independent output: batch ids
    if (t < KNUM) stcs1(out + BOUT + (size_t)bK + t, (float)b);

    // ================= Phase A: warp-specialized 6 dots / 2 edges =================
    if (warp < 6) {
        // 8 lanes per row, 4 rows (chunks) per warp-iter, butterfly reduce
        const int sub = lane & 7;         // lane within 8-group
        const int rg  = lane >> 3;        // row within chunk
        const float4* th4 = reinterpret_cast<const float4*>(theta);
        float4 t0 = th4[sub];
        float4 t1 = th4[sub + 8];
        float4 t2 = th4[sub + 16];
        float4 t3 = th4[sub + 24];

        // chunks c = warp, warp+6, ... (25 chunks of 4 rows); warp 0 gets chunk 24 too
        #pragma unroll 5
        for (int c = warp; c < 25; c += 6) {
            int row = c * 4 + rg;
            const float4* xr = reinterpret_cast<const float4*>(x + (size_t)(base + row) * F_DIM);
            float4 v0 = xr[sub];
            float4 v1 = xr[sub + 8];
            float4 v2 = xr[sub + 16];
            float4 v3 = xr[sub + 24];
            float dA = v0.x * t0.x + v0.y * t0.y + v0.z * t0.z + v0.w * t0.w;
            float dB = v1.x * t1.x + v1.y * t1.y + v1.z * t1.z + v1.w * t1.w;
            dA += v2.x * t2.x + v2.y * t2.y + v2.z * t2.z + v2.w * t2.w;
            dB += v3.x * t3.x + v3.y * t3.y + v3.z * t3.z + v3.w * t3.w;
            float d = dA + dB;
            d += __shfl_xor_sync(FULL, d, 4);
            d += __shfl_xor_sync(FULL, d, 2);
            d += __shfl_xor_sync(FULL, d, 1);
            if (sub == 0) s[row] = d;
        }
    } else {
        // warps 6,7: init z + hist, load+pack 200 int4-groups each, degree histogram
        const int w = warp - 6;            // 0..1
        for (int i = lane; i < NPG; i += 32) {
            degp[w][i] = 0;
            if (w == 0) z[i] = 0.0f;
        }
        __syncwarp();

        const int4* src4 = reinterpret_cast<const int4*>(ei + ebase);
        const int4* dst4 = reinterpret_cast<const int4*>(ei + (size_t)E + ebase);
        const int gbase = w * 200;         // groups [gbase, gbase+200)
        #pragma unroll
        for (int q0 = 0; q0 < 200; q0 += 32) {
            int qi = q0 + lane;            // 0..199 (+ partial tail 192..199)
            unsigned act = __ballot_sync(FULL, qi < 200);
            if (qi < 200) {
                int q = gbase + qi;
                int4 sv = src4[q]; int4 dv = dst4[q];
                int4 pk;
                pk.x = (sv.x - base) | ((dv.x - base) << 7);
                pk.y = (sv.y - base) | ((dv.y - base) << 7);
                pk.z = (sv.z - base) | ((dv.z - base) << 7);
                pk.w = (sv.w - base) | ((dv.w - base) << 7);
                reinterpret_cast<int4*>(packed)[q] = pk;
                int vals[4] = { pk.x & 127, pk.y & 127, pk.z & 127, pk.w & 127 };
                #pragma unroll
                for (int c = 0; c < 4; c++) {
                    unsigned grp = __match_any_sync(act, vals[c]);
                    if ((grp & ((1u << lane) - 1u)) == 0)
                        degp[w][vals[c]] += __popc(grp);
                }
            }
        }
    }
    __syncthreads();

    // ================= per-node: deg, dis, us, self term =================
    if (t < NPG) {
        int d = 1 + degp[0][t] + degp[1][t];
        float fd = (float)d;
        float r  = rsqrtf(fd);
        float sv = s[t];
        dis[t] = r;
        us[t]  = r * sv;
        s[t]   = sv / fd;
    }
    __syncthreads();

    // ================= z[dst] += dis[src]*s[src] : two static blocks =================
    {
        int4 pkA = reinterpret_cast<const int4*>(packed)[t];
        bool hasB = (t + 256) < EPG4;
        int4 pkB = hasB ? reinterpret_cast<const int4*>(packed)[t + 256] : make_int4(0,0,0,0);

        atomicAdd(&z[(pkA.x >> 7) & 127], us[pkA.x & 127]);
        atomicAdd(&z[(pkA.y >> 7) & 127], us[pkA.y & 127]);
        atomicAdd(&z[(pkA.z >> 7) & 127], us[pkA.z & 127]);
        atomicAdd(&z[(pkA.w >> 7) & 127], us[pkA.w & 127]);
        if (hasB) {
            atomicAdd(&z[(pkB.x >> 7) & 127], us[pkB.x & 127]);
            atomicAdd(&z[(pkB.y >> 7) & 127], us[pkB.y & 127]);
            atomicAdd(&z[(pkB.z >> 7) & 127], us[pkB.z & 127]);
            atomicAdd(&z[(pkB.w >> 7) & 127], us[pkB.w & 127]);
        }
    }
    __syncthreads();

    if (t < NPG) z[t] = s[t] + dis[t] * z[t];
    __syncthreads();

    // ================= rank counting, split j-halves =================
    if (t < NPG) {
        float zi = z[t]; int r = 0;
        #pragma unroll 5
        for (int j = 0; j < NPG / 2; j++) {
            float zj = z[j];
            r += (zj > zi) || (zj == zi && j < t);
        }
        rpA[t] = r;
    } else if (t >= 128 && t < 128 + NPG) {
        int i = t - 128;
        float zi = z[i]; int r = 0;
        #pragma unroll 5
        for (int j = NPG / 2; j < NPG; j++) {
            float zj = z[j];
            r += (zj > zi) || (zj == zi && j < i);
        }
        rpB[i] = r;
    }
    __syncthreads();

    // ================= kept flags (registers) + ballots =================
    int k = 0;
    if (t < 128) {
        k = (t < NPG) ? ((rpA[t] + rpB[t]) < KNUM) : 0;
        unsigned bal = __ballot_sync(FULL, k);
        if (lane == 0) wbal[warp] = bal;
    }
    __syncthreads();

    // ================= scan -> codef, inv, scl =================
    if (t < NPG) {
        int off = __popc(wbal[warp] & ((1u << lane) - 1u));
        #pragma unroll
        for (int w = 0; w < 4; w++) if (w < warp) off += __popc(wbal[w]);
        codef[t] = k ? (float)(bK + off) : -1.0f;
        if (k) {
            inv[off] = t;
            scl[off] = 1.0f / (1.0f + __expf(-z[t]));
        }
    }
    __syncthreads();

    // ================= outputs: [x_new | edge0 | edge1] =================
    // x_new: 10 rows per warp, unrolled x2 (two LDG.128 in flight)
    #pragma unroll
    for (int rr = 0; rr < 10; rr += 2) {
        int r0 = warp + 8 * rr, r1 = warp + 8 * (rr + 1);
        int i0 = inv[r0],       i1 = inv[r1];
        float sc0 = scl[r0],    sc1 = scl[r1];
        float4 v0 = reinterpret_cast<const float4*>(x + (size_t)(base + i0) * F_DIM)[lane];
        float4 v1 = reinterpret_cast<const float4*>(x + (size_t)(base + i1) * F_DIM)[lane];
        v0.x *= sc0; v0.y *= sc0; v0.z *= sc0; v0.w *= sc0;
        v1.x *= sc1; v1.y *= sc1; v1.z *= sc1; v1.w *= sc1;
        stcs4(out + (size_t)(bK + r0) * F_DIM + lane * 4, v0);
        stcs4(out + (size_t)(bK + r1) * F_DIM + lane * 4, v1);
    }

    // relabeled edges via codef: two static blocks
    float* e0out = out + EOUT0 + ebase;
    float* e1out = out + EOUT1 + ebase;
    {
        int4 pk = reinterpret_cast<const int4*>(packed)[t];
        float4 o0, o1; float cs, cd;
        cs = codef[pk.x & 127]; cd = codef[(pk.x >> 7) & 127];
        o0.x = (cd < 0.0f) ? -1.0f : cs;  o1.x = (cs < 0.0f) ? -1.0f : cd;
        cs = codef[pk.y & 127]; cd = codef[(pk.y >> 7) & 127];
        o0.y = (cd < 0.0f) ? -1.0f : cs;  o1.y = (cs < 0.0f) ? -1.0f : cd;
        cs = codef[pk.z & 127]; cd = codef[(pk.z >> 7) & 127];
        o0.z = (cd < 0.0f) ? -1.0f : cs;  o1.z = (cs < 0.0f) ? -1.0f : cd;
        cs = codef[pk.w & 127]; cd = codef[(pk.w >> 7) & 127];
        o0.w = (cd < 0.0f) ? -1.0f : cs;  o1.w = (cs < 0.0f) ? -1.0f : cd;
        stcs4(e0out + t * 4, o0);
        stcs4(e1out + t * 4, o1);
    }
    if (t + 256 < EPG4) {
        int q = t + 256;
        int4 pk = reinterpret_cast<const int4*>(packed)[q];
        float4 o0, o1; float cs, cd;
        cs = codef[pk.x & 127]; cd = codef[(pk.x >> 7) & 127];
        o0.x = (cd < 0.0f) ? -1.0f : cs;  o1.x = (cs < 0.0f) ? -1.0f : cd;
        cs = codef[pk.y & 127]; cd = codef[(pk.y >> 7) & 127];
        o0.y = (cd < 0.0f) ? -1.0f : cs;  o1.y = (cs < 0.0f) ? -1.0f : cd;
        cs = codef[pk.z & 127]; cd = codef[(pk.z >> 7) & 127];
        o0.z = (cd < 0.0f) ? -1.0f : cs;  o1.z = (cs < 0.0f) ? -1.0f : cd;
        cs = codef[pk.w & 127]; cd = codef[(pk.w >> 7) & 127];
        o0.w = (cd < 0.0f) ? -1.0f : cs;  o1.w = (cs < 0.0f) ? -1.0f : cd;
        stcs4(e0out + q * 4, o0);
        stcs4(e1out + q * 4, o1);
    }
}

extern "C" void kernel_launch(void* const* d_in, const int* in_sizes, int n_in,
                              void* d_out, int out_size)
{
    const float* x     = (const float*)d_in[0];
    const int*   ei    = (const int*)d_in[1];
    const float* theta = (const float*)d_in[3];
    float* out = (float*)d_out;

    int N = in_sizes[0] / F_DIM;   // 100000
    int E = in_sizes[1] / 2;       // 1600000
    int B = N / NPG;               // 1000

    sagpool_fused_kernel<<<B, TPB>>>(x, ei, theta, out, E, B);
}